// round 1
// baseline (speedup 1.0000x reference)
#include <cuda_runtime.h>

// Problem constants: labels [16, 8, 512, 512] float32
#define HH 512
#define WW 512
#define NIMG 128                 // 16*8
#define ROWS 32                  // output rows per band
#define BANDS (HH / ROWS)        // 16
#define STRIPS 4                 // 4 strips of 128 cols
#define WPB 8                    // warps per block
#define NBLOCKS ((NIMG * BANDS * STRIPS) / WPB)  // 1024
#define INV_N (1.0f / 33554432.0f)

__device__ float g_partials[NBLOCKS];

__global__ __launch_bounds__(256, 8) void open_mse_kernel(const float* __restrict__ x) {
    const int tid  = threadIdx.x;
    const int wid  = tid >> 5;
    const int lane = tid & 31;
    const int gw   = blockIdx.x * WPB + wid;   // global warp id, [0, 8192)

    const int strip = gw & 3;                  // 0..3
    const int band  = (gw >> 2) & (BANDS - 1); // 0..15
    const int img   = gw >> 6;                 // 0..127

    const int c0 = strip * 128;
    const int r0 = band * ROWS;
    const int r1 = r0 + ROWS;                  // <= HH
    const bool leftEdge  = (c0 == 0);
    const bool rightEdge = (c0 + 128 >= WW);

    const float* base = x + (size_t)img * (HH * WW);
    const int col = c0 + lane * 4;
    const int haloL = leftEdge ? 0 : (c0 - 1);
    const int haloR = rightEdge ? (WW - 1) : (c0 + 128);

    const bool doL = (lane == 0) && !leftEdge;
    const bool doH = (lane == 31) && !rightEdge;

    float acc = 0.f;

    // ---- prologue: rowmin of row ra = max(r0-1, 0)  (reflect at top) ----
    const int ra = (r0 > 0) ? (r0 - 1) : 0;
    float4 xv = *(const float4*)(base + (size_t)ra * WW + col);
    float  xL = doL ? base[(size_t)ra * WW + haloL] : 0.f;
    float  xH = doH ? base[(size_t)ra * WW + haloR] : 0.f;

    float left = __shfl_up_sync(0xffffffffu, xv.w, 1);
    if (lane == 0) left = leftEdge ? xv.x : xL;

    float4 rm_prev;
    rm_prev.x = fminf(left, xv.x);
    rm_prev.y = fminf(xv.x, xv.y);
    rm_prev.z = fminf(xv.y, xv.z);
    rm_prev.w = fminf(xv.z, xv.w);
    float rmH_prev = fminf(xv.w, xH);          // meaningful only for interior lane31

    float4 er_prev = make_float4(0.f, 0.f, 0.f, 0.f);
    float4 x_prev  = make_float4(0.f, 0.f, 0.f, 0.f);
    float  erH_prev = 0.f;

    const int e_max = (r1 < HH) ? r1 : (HH - 1);

    // prefetch row r0
    float4 xnext = *(const float4*)(base + (size_t)r0 * WW + col);
    float  xLn = doL ? base[(size_t)r0 * WW + haloL] : 0.f;
    float  xHn = doH ? base[(size_t)r0 * WW + haloR] : 0.f;

    for (int e = r0; e <= e_max; ++e) {
        xv = xnext; xL = xLn; xH = xHn;
        if (e < e_max) {
            const int rn = e + 1;
            xnext = *(const float4*)(base + (size_t)rn * WW + col);
            xLn = doL ? base[(size_t)rn * WW + haloL] : 0.f;
            xHn = doH ? base[(size_t)rn * WW + haloR] : 0.f;
        }

        // horizontal min (erosion, offsets {-1,0}, reflect at col 0)
        float l = __shfl_up_sync(0xffffffffu, xv.w, 1);
        if (lane == 0) l = leftEdge ? xv.x : xL;
        float4 rm;
        rm.x = fminf(l,    xv.x);
        rm.y = fminf(xv.x, xv.y);
        rm.z = fminf(xv.y, xv.z);
        rm.w = fminf(xv.z, xv.w);

        // vertical min -> eroded row e
        float4 er;
        er.x = fminf(rm_prev.x, rm.x);
        er.y = fminf(rm_prev.y, rm.y);
        er.z = fminf(rm_prev.z, rm.z);
        er.w = fminf(rm_prev.w, rm.w);

        // halo column J = c0+128 (lane 31, interior strips)
        const float rmH = fminf(xv.w, xH);
        const float erH = fminf(rmH_prev, rmH);

        if (e > r0) {
            // output row i = e-1: vmax = max(eroded[i], eroded[i+1])
            float4 vm;
            vm.x = fmaxf(er_prev.x, er.x);
            vm.y = fmaxf(er_prev.y, er.y);
            vm.z = fmaxf(er_prev.z, er.z);
            vm.w = fmaxf(er_prev.w, er.w);
            const float vmH = fmaxf(erH_prev, erH);

            float right = __shfl_down_sync(0xffffffffu, vm.x, 1);
            if (lane == 31) right = rightEdge ? vm.w : vmH;

            float4 op;
            op.x = fmaxf(vm.x, vm.y);
            op.y = fmaxf(vm.y, vm.z);
            op.z = fmaxf(vm.z, vm.w);
            op.w = fmaxf(vm.w, right);

            const float d0 = x_prev.x - op.x;
            const float d1 = x_prev.y - op.y;
            const float d2 = x_prev.z - op.z;
            const float d3 = x_prev.w - op.w;
            acc += d0 * d0 + d1 * d1 + d2 * d2 + d3 * d3;
        }

        er_prev = er; x_prev = xv; rm_prev = rm;
        rmH_prev = rmH; erH_prev = erH;
    }

    // ---- epilogue: bottom band emits row H-1 (dilation clamps i+1 -> H-1) ----
    if (r1 == HH) {
        const float4 vm = er_prev;          // max(er[H-1], er[H-1])
        const float vmH = erH_prev;
        float right = __shfl_down_sync(0xffffffffu, vm.x, 1);
        if (lane == 31) right = rightEdge ? vm.w : vmH;
        float4 op;
        op.x = fmaxf(vm.x, vm.y);
        op.y = fmaxf(vm.y, vm.z);
        op.z = fmaxf(vm.z, vm.w);
        op.w = fmaxf(vm.w, right);
        const float d0 = x_prev.x - op.x;
        const float d1 = x_prev.y - op.y;
        const float d2 = x_prev.z - op.z;
        const float d3 = x_prev.w - op.w;
        acc += d0 * d0 + d1 * d1 + d2 * d2 + d3 * d3;
    }

    // ---- block reduction -> g_partials[blockIdx.x] ----
    #pragma unroll
    for (int o = 16; o > 0; o >>= 1)
        acc += __shfl_xor_sync(0xffffffffu, acc, o);

    __shared__ float s[WPB];
    if (lane == 0) s[wid] = acc;
    __syncthreads();
    if (tid == 0) {
        float t = 0.f;
        #pragma unroll
        for (int i = 0; i < WPB; ++i) t += s[i];
        g_partials[blockIdx.x] = t;
    }
}

__global__ void reduce_kernel(float* __restrict__ out) {
    __shared__ float s[256];
    const int t = threadIdx.x;
    float a = 0.f;
    for (int i = t; i < NBLOCKS; i += 256) a += g_partials[i];
    s[t] = a;
    __syncthreads();
    #pragma unroll
    for (int o = 128; o > 0; o >>= 1) {
        if (t < o) s[t] += s[t + o];
        __syncthreads();
    }
    if (t == 0) out[0] = s[0] * INV_N;
}

extern "C" void kernel_launch(void* const* d_in, const int* in_sizes, int n_in,
                              void* d_out, int out_size) {
    (void)in_sizes; (void)n_in; (void)out_size;
    const float* labels = (const float*)d_in[0];
    float* out = (float*)d_out;
    open_mse_kernel<<<NBLOCKS, 256>>>(labels);
    reduce_kernel<<<1, 256>>>(out);
}

// round 2
// speedup vs baseline: 1.6806x; 1.6806x over previous
#include <cuda_runtime.h>

// Problem constants: labels [16, 8, 512, 512] float32
#define HH 512
#define WW 512
#define NIMG 128                 // 16*8
#define ROWS 32                  // output rows per band
#define BANDS (HH / ROWS)        // 16
#define STRIPS 4                 // 4 strips of 128 cols
#define WPB 8                    // warps per block
#define NBLOCKS ((NIMG * BANDS * STRIPS) / WPB)  // 1024
#define INV_N (1.0f / 33554432.0f)

__device__ float g_partials[NBLOCKS];
__device__ unsigned int g_counter = 0;

__global__ __launch_bounds__(256) void open_mse_kernel(const float* __restrict__ x,
                                                       float* __restrict__ out) {
    const int tid  = threadIdx.x;
    const int wid  = tid >> 5;
    const int lane = tid & 31;
    const int gw   = blockIdx.x * WPB + wid;   // global warp id, [0, 8192)

    const int strip = gw & 3;                  // 0..3
    const int band  = (gw >> 2) & (BANDS - 1); // 0..15
    const int img   = gw >> 6;                 // 0..127

    const int c0 = strip * 128;
    const int r0 = band * ROWS;
    const int r1 = r0 + ROWS;                  // <= HH
    const bool leftEdge  = (c0 == 0);
    const bool rightEdge = (c0 + 128 >= WW);

    const float* base = x + (size_t)img * (HH * WW);
    const int col = c0 + lane * 4;
    const int haloL = leftEdge ? 0 : (c0 - 1);
    const int haloR = rightEdge ? (WW - 1) : (c0 + 128);

    const bool doL = (lane == 0) && !leftEdge;
    const bool doH = (lane == 31) && !rightEdge;

    float acc = 0.f;

    // ---- prologue: rowmin of row ra = max(r0-1, 0)  (reflect at top) ----
    const int ra = (r0 > 0) ? (r0 - 1) : 0;
    float4 xv = *(const float4*)(base + (size_t)ra * WW + col);
    float  xL = doL ? base[(size_t)ra * WW + haloL] : 0.f;
    float  xH = doH ? base[(size_t)ra * WW + haloR] : 0.f;

    float left = __shfl_up_sync(0xffffffffu, xv.w, 1);
    if (lane == 0) left = leftEdge ? xv.x : xL;

    float4 rm_prev;
    rm_prev.x = fminf(left, xv.x);
    rm_prev.y = fminf(xv.x, xv.y);
    rm_prev.z = fminf(xv.y, xv.z);
    rm_prev.w = fminf(xv.z, xv.w);
    float rmH_prev = fminf(xv.w, xH);          // meaningful only for interior lane31

    float4 er_prev = make_float4(0.f, 0.f, 0.f, 0.f);
    float4 x_prev  = make_float4(0.f, 0.f, 0.f, 0.f);
    float  erH_prev = 0.f;

    const int e_max = (r1 < HH) ? r1 : (HH - 1);

    // prefetch row r0
    float4 xnext = *(const float4*)(base + (size_t)r0 * WW + col);
    float  xLn = doL ? base[(size_t)r0 * WW + haloL] : 0.f;
    float  xHn = doH ? base[(size_t)r0 * WW + haloR] : 0.f;

    for (int e = r0; e <= e_max; ++e) {
        xv = xnext; xL = xLn; xH = xHn;
        if (e < e_max) {
            const int rn = e + 1;
            xnext = *(const float4*)(base + (size_t)rn * WW + col);
            xLn = doL ? base[(size_t)rn * WW + haloL] : 0.f;
            xHn = doH ? base[(size_t)rn * WW + haloR] : 0.f;
        }

        // horizontal min (erosion, offsets {-1,0}, reflect at col 0)
        float l = __shfl_up_sync(0xffffffffu, xv.w, 1);
        if (lane == 0) l = leftEdge ? xv.x : xL;
        float4 rm;
        rm.x = fminf(l,    xv.x);
        rm.y = fminf(xv.x, xv.y);
        rm.z = fminf(xv.y, xv.z);
        rm.w = fminf(xv.z, xv.w);

        // vertical min -> eroded row e
        float4 er;
        er.x = fminf(rm_prev.x, rm.x);
        er.y = fminf(rm_prev.y, rm.y);
        er.z = fminf(rm_prev.z, rm.z);
        er.w = fminf(rm_prev.w, rm.w);

        // halo column J = c0+128 (lane 31, interior strips)
        const float rmH = fminf(xv.w, xH);
        const float erH = fminf(rmH_prev, rmH);

        if (e > r0) {
            // output row i = e-1: vmax = max(eroded[i], eroded[i+1])
            float4 vm;
            vm.x = fmaxf(er_prev.x, er.x);
            vm.y = fmaxf(er_prev.y, er.y);
            vm.z = fmaxf(er_prev.z, er.z);
            vm.w = fmaxf(er_prev.w, er.w);
            const float vmH = fmaxf(erH_prev, erH);

            float right = __shfl_down_sync(0xffffffffu, vm.x, 1);
            if (lane == 31) right = rightEdge ? vm.w : vmH;

            float4 op;
            op.x = fmaxf(vm.x, vm.y);
            op.y = fmaxf(vm.y, vm.z);
            op.z = fmaxf(vm.z, vm.w);
            op.w = fmaxf(vm.w, right);

            const float d0 = x_prev.x - op.x;
            const float d1 = x_prev.y - op.y;
            const float d2 = x_prev.z - op.z;
            const float d3 = x_prev.w - op.w;
            acc += d0 * d0 + d1 * d1 + d2 * d2 + d3 * d3;
        }

        er_prev = er; x_prev = xv; rm_prev = rm;
        rmH_prev = rmH; erH_prev = erH;
    }

    // ---- epilogue: bottom band emits row H-1 (dilation clamps i+1 -> H-1) ----
    if (r1 == HH) {
        const float4 vm = er_prev;          // max(er[H-1], er[H-1])
        const float vmH = erH_prev;
        float right = __shfl_down_sync(0xffffffffu, vm.x, 1);
        if (lane == 31) right = rightEdge ? vm.w : vmH;
        float4 op;
        op.x = fmaxf(vm.x, vm.y);
        op.y = fmaxf(vm.y, vm.z);
        op.z = fmaxf(vm.z, vm.w);
        op.w = fmaxf(vm.w, right);
        const float d0 = x_prev.x - op.x;
        const float d1 = x_prev.y - op.y;
        const float d2 = x_prev.z - op.z;
        const float d3 = x_prev.w - op.w;
        acc += d0 * d0 + d1 * d1 + d2 * d2 + d3 * d3;
    }

    // ---- block reduction -> g_partials[blockIdx.x] ----
    #pragma unroll
    for (int o = 16; o > 0; o >>= 1)
        acc += __shfl_xor_sync(0xffffffffu, acc, o);

    __shared__ float s[WPB];
    __shared__ bool s_last;
    if (lane == 0) s[wid] = acc;
    __syncthreads();
    if (tid == 0) {
        float t = 0.f;
        #pragma unroll
        for (int i = 0; i < WPB; ++i) t += s[i];
        g_partials[blockIdx.x] = t;
        __threadfence();
        unsigned int old = atomicAdd(&g_counter, 1u);
        s_last = (old == NBLOCKS - 1);
    }
    __syncthreads();

    // ---- last block: deterministic fixed-order final reduction ----
    if (s_last) {
        float a = 0.f;
        for (int i = tid; i < NBLOCKS; i += 256) a += g_partials[i];
        #pragma unroll
        for (int o = 16; o > 0; o >>= 1)
            a += __shfl_xor_sync(0xffffffffu, a, o);
        __shared__ float s2[WPB];
        if (lane == 0) s2[wid] = a;
        __syncthreads();
        if (tid == 0) {
            float t = 0.f;
            #pragma unroll
            for (int i = 0; i < WPB; ++i) t += s2[i];
            out[0] = t * INV_N;
            g_counter = 0;   // self-reset for next launch / graph replay
        }
    }
}

extern "C" void kernel_launch(void* const* d_in, const int* in_sizes, int n_in,
                              void* d_out, int out_size) {
    (void)in_sizes; (void)n_in; (void)out_size;
    const float* labels = (const float*)d_in[0];
    float* out = (float*)d_out;
    open_mse_kernel<<<NBLOCKS, 256>>>(labels, out);
}

// round 6
// speedup vs baseline: 1.6818x; 1.0007x over previous
#include <cuda_runtime.h>

// labels [16, 8, 512, 512] float32
#define HH 512
#define WW 512
#define NIMG 128                  // 16*8
#define ROWS 32                   // output rows per band
#define BANDS (HH / ROWS)         // 16
#define STRIPS 2                  // 2 strips of 256 cols (8 cols/thread)
#define WPB 4                     // warps per block (128 threads)
#define NBLOCKS ((NIMG * BANDS * STRIPS) / WPB)   // 1024
#define INV_N (1.0f / 33554432.0f)

__device__ float g_partials[NBLOCKS];
__device__ unsigned int g_counter = 0;

__global__ __launch_bounds__(128) void open_mse_kernel(const float* __restrict__ x,
                                                       float* __restrict__ out) {
    const int tid  = threadIdx.x;
    const int wid  = tid >> 5;
    const int lane = tid & 31;
    const int gw   = blockIdx.x * WPB + wid;     // [0, 4096)

    const int strip = gw & 1;                    // 0..1
    const int band  = (gw >> 1) & (BANDS - 1);   // 0..15
    const int img   = gw >> 5;                   // 0..127

    const int c0 = strip * 256;
    const int r0 = band * ROWS;
    const int r1 = r0 + ROWS;
    const bool leftEdge  = (c0 == 0);
    const bool rightEdge = (c0 + 256 >= WW);

    const float* base = x + (size_t)img * (HH * WW);
    const int c = c0 + lane * 8;
    const bool doL = (lane == 0)  && !leftEdge;
    const bool doH = (lane == 31) && !rightEdge;
    const int haloL = leftEdge ? 0 : (c0 - 1);
    const int haloR = rightEdge ? (WW - 1) : (c0 + 256);

    float rm_prev[8], er_prev[8], x_prev[8];
    float rmH_prev, erH_prev = 0.f;
    float acc = 0.f;

    // ---- prologue: rowmin of row ra = max(r0-1, 0)  (reflect at top) ----
    {
        const int ra = (r0 > 0) ? (r0 - 1) : 0;
        const float4* pa = (const float4*)(base + (size_t)ra * WW + c);
        float4 v0 = pa[0], v1 = pa[1];
        float a[8] = {v0.x, v0.y, v0.z, v0.w, v1.x, v1.y, v1.z, v1.w};
        float xL = doL ? base[(size_t)ra * WW + haloL] : 0.f;
        float xH = doH ? base[(size_t)ra * WW + haloR] : 0.f;
        float left = __shfl_up_sync(0xffffffffu, a[7], 1);
        if (lane == 0) left = leftEdge ? a[0] : xL;
        rm_prev[0] = fminf(left, a[0]);
        #pragma unroll
        for (int j = 1; j < 8; ++j) rm_prev[j] = fminf(a[j - 1], a[j]);
        rmH_prev = fminf(a[7], xH);
    }

    const int e_max = (r1 < HH) ? r1 : (HH - 1);

    // bumped pointers, starting at row r0
    const float4* p  = (const float4*)(base + (size_t)r0 * WW + c);
    const float*  pL = base + (size_t)r0 * WW + haloL;
    const float*  pH = base + (size_t)r0 * WW + haloR;

    // prefetch row r0
    float4 v0 = p[0], v1 = p[1];
    float  xL = doL ? *pL : 0.f;
    float  xH = doH ? *pH : 0.f;
    p += WW / 4; pL += WW; pH += WW;

    // ---- peeled first row: e = r0 (erosion only, no output) ----
    {
        float a[8] = {v0.x, v0.y, v0.z, v0.w, v1.x, v1.y, v1.z, v1.w};
        // prefetch row r0+1 (always exists: r0+1 <= 481 <= 511)
        v0 = p[0]; v1 = p[1];
        float xLn = doL ? *pL : 0.f;
        float xHn = doH ? *pH : 0.f;
        p += WW / 4; pL += WW; pH += WW;

        float left = __shfl_up_sync(0xffffffffu, a[7], 1);
        if (lane == 0) left = leftEdge ? a[0] : xL;
        float rm[8];
        rm[0] = fminf(left, a[0]);
        #pragma unroll
        for (int j = 1; j < 8; ++j) rm[j] = fminf(a[j - 1], a[j]);
        #pragma unroll
        for (int j = 0; j < 8; ++j) {
            er_prev[j] = fminf(rm_prev[j], rm[j]);
            rm_prev[j] = rm[j];
            x_prev[j]  = a[j];
        }
        float rmH = fminf(a[7], xH);
        erH_prev = fminf(rmH_prev, rmH);
        rmH_prev = rmH;
        xL = xLn; xH = xHn;
    }

    // ---- steady state: e = r0+1 .. e_max, output row e-1 each iter ----
    for (int e = r0 + 1; e <= e_max; ++e) {
        float a[8] = {v0.x, v0.y, v0.z, v0.w, v1.x, v1.y, v1.z, v1.w};
        float xLn = 0.f, xHn = 0.f;
        if (e < e_max) {                       // row e+1 exists and is needed
            v0 = p[0]; v1 = p[1];
            xLn = doL ? *pL : 0.f;
            xHn = doH ? *pH : 0.f;
        }
        p += WW / 4; pL += WW; pH += WW;       // pointer bump only, never deref OOB

        // horizontal min (erosion offsets {-1,0}, reflect at col 0)
        float left = __shfl_up_sync(0xffffffffu, a[7], 1);
        if (lane == 0) left = leftEdge ? a[0] : xL;
        float rm[8];
        rm[0] = fminf(left, a[0]);
        #pragma unroll
        for (int j = 1; j < 8; ++j) rm[j] = fminf(a[j - 1], a[j]);

        // vertical min -> eroded row e; vertical max with previous eroded row
        float er[8], vm[8];
        #pragma unroll
        for (int j = 0; j < 8; ++j) {
            er[j] = fminf(rm_prev[j], rm[j]);
            vm[j] = fmaxf(er_prev[j], er[j]);
        }
        const float rmH = fminf(a[7], xH);
        const float erH = fminf(rmH_prev, rmH);
        const float vmH = fmaxf(erH_prev, erH);

        // horizontal max (dilation offsets {0,+1}, clamp at right edge)
        float right = __shfl_down_sync(0xffffffffu, vm[0], 1);
        if (lane == 31) right = rightEdge ? vm[7] : vmH;
        float op[8];
        #pragma unroll
        for (int j = 0; j < 7; ++j) op[j] = fmaxf(vm[j], vm[j + 1]);
        op[7] = fmaxf(vm[7], right);

        #pragma unroll
        for (int j = 0; j < 8; ++j) {
            const float d = x_prev[j] - op[j];
            acc += d * d;
        }

        #pragma unroll
        for (int j = 0; j < 8; ++j) {
            er_prev[j] = er[j];
            rm_prev[j] = rm[j];
            x_prev[j]  = a[j];
        }
        erH_prev = erH; rmH_prev = rmH;
        xL = xLn; xH = xHn;
    }

    // ---- epilogue: bottom band emits row H-1 (dilation clamps i+1 -> H-1) ----
    if (r1 == HH) {
        float right = __shfl_down_sync(0xffffffffu, er_prev[0], 1);
        if (lane == 31) right = rightEdge ? er_prev[7] : erH_prev;
        float op[8];
        #pragma unroll
        for (int j = 0; j < 7; ++j) op[j] = fmaxf(er_prev[j], er_prev[j + 1]);
        op[7] = fmaxf(er_prev[7], right);
        #pragma unroll
        for (int j = 0; j < 8; ++j) {
            const float d = x_prev[j] - op[j];
            acc += d * d;
        }
    }

    // ---- block reduction -> g_partials[blockIdx.x] ----
    #pragma unroll
    for (int o = 16; o > 0; o >>= 1)
        acc += __shfl_xor_sync(0xffffffffu, acc, o);

    __shared__ float s[WPB];
    __shared__ bool s_last;
    if (lane == 0) s[wid] = acc;
    __syncthreads();
    if (tid == 0) {
        float t = 0.f;
        #pragma unroll
        for (int i = 0; i < WPB; ++i) t += s[i];
        g_partials[blockIdx.x] = t;
        __threadfence();
        unsigned int old = atomicAdd(&g_counter, 1u);
        s_last = (old == NBLOCKS - 1);
    }
    __syncthreads();

    // ---- last block: deterministic fixed-order final reduction ----
    if (s_last) {
        float a = 0.f;
        for (int i = tid; i < NBLOCKS; i += 128) a += g_partials[i];
        #pragma unroll
        for (int o = 16; o > 0; o >>= 1)
            a += __shfl_xor_sync(0xffffffffu, a, o);
        __shared__ float s2[WPB];
        if (lane == 0) s2[wid] = a;
        __syncthreads();
        if (tid == 0) {
            float t = 0.f;
            #pragma unroll
            for (int i = 0; i < WPB; ++i) t += s2[i];
            out[0] = t * INV_N;
            g_counter = 0;   // self-reset for next launch / graph replay
        }
    }
}

extern "C" void kernel_launch(void* const* d_in, const int* in_sizes, int n_in,
                              void* d_out, int out_size) {
    (void)in_sizes; (void)n_in; (void)out_size;
    const float* labels = (const float*)d_in[0];
    float* out = (float*)d_out;
    open_mse_kernel<<<NBLOCKS, 128>>>(labels, out);
}